// round 4
// baseline (speedup 1.0000x reference)
#include <cuda_runtime.h>
#include <cuda_fp16.h>
#include <cstdint>
#include <cstddef>

// Problem dims
#define S_DIM  128
#define I_DIM  384
#define INJ    256   // IN_DIM
#define PD     32    // PROJ_DIM
#define PD2    64
#define F_DIM  128   // OUT_DIM
#define MROWS  (I_DIM*PD)       // 12288

// ---------------- scratch (device globals; no allocation allowed) ----------
__device__ __align__(16) __half g_L[MROWS * S_DIM];   // [(i*32+d)][s]  3.1 MB
__device__ __align__(16) __half g_R[MROWS * S_DIM];   // [(j*32+e)][s]  3.1 MB
__device__ __align__(16) __half g_Wt[F_DIM * 1024];   // [f][(d*32+e)]  256 KB
__device__ float g_norm[I_DIM * I_DIM];

// ---------------- helpers --------------------------------------------------
__device__ __forceinline__ uint32_t s32(const void* p) {
    return (uint32_t)__cvta_generic_to_shared(p);
}
__device__ __forceinline__ void ldsm4(uint32_t& r0, uint32_t& r1, uint32_t& r2,
                                      uint32_t& r3, uint32_t a) {
    asm volatile("ldmatrix.sync.aligned.m8n8.x4.shared.b16 {%0,%1,%2,%3}, [%4];"
                 : "=r"(r0), "=r"(r1), "=r"(r2), "=r"(r3) : "r"(a));
}
__device__ __forceinline__ void cp16(uint32_t dst, const void* src) {
    asm volatile("cp.async.ca.shared.global [%0], [%1], 16;" :: "r"(dst), "l"(src));
}
#define CP_COMMIT() asm volatile("cp.async.commit_group;")
#define CP_WAIT0()  asm volatile("cp.async.wait_group 0;")

#define MMA_16816(C, A, B)                                                      \
    asm volatile("mma.sync.aligned.m16n8k16.row.col.f32.f16.f16.f32 "           \
                 "{%0,%1,%2,%3}, {%4,%5,%6,%7}, {%8,%9}, {%0,%1,%2,%3};"        \
                 : "+f"((C)[0]), "+f"((C)[1]), "+f"((C)[2]), "+f"((C)[3])       \
                 : "r"((A)[0]), "r"((A)[1]), "r"((A)[2]), "r"((A)[3]),          \
                   "r"((B)[0]), "r"((B)[1]))

// ---------------- K1: layernorm + projection + mask -> L,R (fp16 rn) -------
__global__ __launch_bounds__(256) void k_ln_proj(const float* __restrict__ x,
                                                 const float* __restrict__ mask,
                                                 const float* __restrict__ Wp,
                                                 const float* __restrict__ bp) {
    int row = blockIdx.x;              // row = s*384 + i
    int s = row / I_DIM;
    int i = row - s * I_DIM;
    int t = threadIdx.x;

    __shared__ float xs[INJ];
    __shared__ float rs[8], rq[8];
    __shared__ float pacc[256];

    float v = x[(size_t)row * INJ + t];
    float sum = v, sq = v * v;
#pragma unroll
    for (int o = 16; o > 0; o >>= 1) {
        sum += __shfl_xor_sync(0xffffffffu, sum, o);
        sq  += __shfl_xor_sync(0xffffffffu, sq, o);
    }
    if ((t & 31) == 0) { rs[t >> 5] = sum; rq[t >> 5] = sq; }
    __syncthreads();
    float ts = 0.f, tq = 0.f;
#pragma unroll
    for (int w = 0; w < 8; w++) { ts += rs[w]; tq += rq[w]; }
    float mean = ts * (1.f / INJ);
    float var  = tq * (1.f / INJ) - mean * mean;
    float rstd = rsqrtf(var + 1e-5f);
    xs[t] = (v - mean) * rstd;
    __syncthreads();

    int c = t & 63, q = t >> 6;
    float acc = 0.f;
    int k0 = q * 64;
#pragma unroll 4
    for (int k = k0; k < k0 + 64; k++) acc += xs[k] * Wp[k * PD2 + c];
    pacc[t] = acc;
    __syncthreads();
    if (q == 0) {
        float tot = pacc[c] + pacc[c + 64] + pacc[c + 128] + pacc[c + 192] + bp[c];
        tot *= mask[row];
        __half h = __float2half_rn(tot);
        if (c < PD) g_L[((size_t)(i * PD + c)) * S_DIM + s] = h;
        else        g_R[((size_t)(i * PD + (c - PD))) * S_DIM + s] = h;
    }
}

// ---------------- K2: transpose out_weights -> Wt[f][d*32+e] (fp16 rn) -----
__global__ __launch_bounds__(256) void k_wt(const float* __restrict__ w) {
    int idx = blockIdx.x * 256 + threadIdx.x;   // idx = f*1024 + de
    int f  = idx >> 10;
    int de = idx & 1023;
    g_Wt[idx] = __float2half_rn(w[de * F_DIM + f]);
}

// ---------------- K3: norm[i][j] = sum_s mask[s][i]*mask[s][j] -------------
__global__ __launch_bounds__(256) void k_norm(const float* __restrict__ mask) {
    __shared__ float mi[16], mj[16];
    int t = threadIdx.x;
    int tx = t & 15, ty = t >> 4;
    int i0 = blockIdx.x * 16, j0 = blockIdx.y * 16;
    float acc = 0.f;
    for (int s = 0; s < S_DIM; s++) {
        if (t < 16)      mi[t]      = mask[s * I_DIM + i0 + t];
        else if (t < 32) mj[t - 16] = mask[s * I_DIM + j0 + (t - 16)];
        __syncthreads();
        acc += mi[ty] * mj[tx];
        __syncthreads();
    }
    g_norm[(i0 + ty) * I_DIM + j0 + tx] = acc;
}

// ---------------- K4: FUSED outer-product + contraction --------------------
// Grid (96, 48): CTA covers i-tile of 4 (bm) x j-tile of 8 (bn).
// Phase 1: 128x256 tile of G = L * R^T (K=128) with 16 warps (4x4, 32x64 each)
//          -> re-laid out into smem A2[32][1024] fp16 ([(i*8+j)][(d*32+e)]).
// Phase 2: out[32][128] = A2 * Wt^T (K=1024), cp.async double-buffered Wt,
//          epilogue bias + 1/(norm+1e-3).
// Dynamic smem layout (bytes):
//   As : [128][136] half @      0   (34816)
//   Bs : [256][136] half @  34816   (69632)   (phase-2 reuses as 2x Ws[128][72])
//   A2 : [ 32][1032] half @ 104448  (66048)   total 170496
#define SM_FUSED 170496

__global__ __launch_bounds__(512, 1) void k_fused(const float* __restrict__ obias,
                                                  float* __restrict__ out) {
    extern __shared__ char sm_[];
    __half* As = (__half*)sm_;
    __half* Bs = (__half*)(sm_ + 34816);
    __half* A2 = (__half*)(sm_ + 104448);
    __half* Ws = (__half*)(sm_ + 34816);      // two buffers of [128][72] (18432 B each)

    int tid = threadIdx.x, lane = tid & 31, wid = tid >> 5;
    int bm = blockIdx.x, bn = blockIdx.y;
    int g = lane >> 2, tg = lane & 3;

    // ---- phase-1 tile loads (L rows bm*128.., R rows bn*256..) ----
    const __half* Lg = g_L + (size_t)bm * 128 * S_DIM;
    const __half* Rg = g_R + (size_t)bn * 256 * S_DIM;
#pragma unroll
    for (int it = 0; it < 4; it++) {
        int idx = tid + it * 512; int r = idx >> 4, c = (idx & 15) * 8;
        *(uint4*)(As + r * 136 + c) = *(const uint4*)(Lg + r * S_DIM + c);
    }
#pragma unroll
    for (int it = 0; it < 8; it++) {
        int idx = tid + it * 512; int r = idx >> 4, c = (idx & 15) * 8;
        *(uint4*)(Bs + r * 136 + c) = *(const uint4*)(Rg + r * S_DIM + c);
    }
    __syncthreads();

    // ---- phase-1 compute: warp (wm, wn) of 4x4, warp tile 32x64 ----
    int wm = wid & 3, wn = wid >> 2;
    int l15  = lane & 15;
    int acol = (lane >> 4) << 3;                      // 0 or 8
    int brow = (lane & 7) + ((lane >> 4) << 3);       // 0-7 or 8-15
    int bcol = ((lane >> 3) & 1) << 3;                // 0 or 8

    uint32_t aB = s32(As) + (uint32_t)(((wm * 32 + l15) * 136 + acol) * 2);
    uint32_t bB = s32(Bs) + (uint32_t)(((wn * 64 + brow) * 136 + bcol) * 2);

    float c1[2][8][4];
#pragma unroll
    for (int a = 0; a < 2; a++)
#pragma unroll
        for (int b = 0; b < 8; b++)
#pragma unroll
            for (int k = 0; k < 4; k++) c1[a][b][k] = 0.f;

#pragma unroll
    for (int kk = 0; kk < 8; kk++) {
        uint32_t a[2][4], b[8][2];
        ldsm4(a[0][0], a[0][1], a[0][2], a[0][3], aB + kk * 32);
        ldsm4(a[1][0], a[1][1], a[1][2], a[1][3], aB + 16 * 136 * 2 + kk * 32);
#pragma unroll
        for (int p = 0; p < 4; p++)
            ldsm4(b[2 * p][0], b[2 * p][1], b[2 * p + 1][0], b[2 * p + 1][1],
                  bB + p * 16 * 136 * 2 + kk * 32);
#pragma unroll
        for (int mi = 0; mi < 2; mi++)
#pragma unroll
            for (int ni = 0; ni < 8; ni++)
                MMA_16816(c1[mi][ni], a[mi], b[ni]);
    }

    // ---- phase-1 epilogue: scatter to A2[(i*8+j)][(d*32+e)] fp16 ----
#pragma unroll
    for (int mi = 0; mi < 2; mi++) {
#pragma unroll
        for (int ni = 0; ni < 8; ni++) {
            int r0 = wm * 32 + mi * 16 + g;
            int n0 = wn * 64 + ni * 8 + tg * 2;
            int i_ = r0 >> 5, d = r0 & 31;
            int j_ = n0 >> 5, e = n0 & 31;
            int row = i_ * 8 + j_;
            *(__half2*)(A2 + row * 1032 + d * 32 + e) =
                __floats2half2_rn(c1[mi][ni][0], c1[mi][ni][1]);
            *(__half2*)(A2 + row * 1032 + (d + 8) * 32 + e) =
                __floats2half2_rn(c1[mi][ni][2], c1[mi][ni][3]);
        }
    }
    __syncthreads();   // A2 complete; Bs region free for Ws reuse

    // ---- phase 2: out[32][128] = A2 * Wt^T, K = 1024 in 16 chunks ----
    int wm2 = wid & 1, wn2 = wid >> 1;
    uint32_t a2B = s32(A2) + (uint32_t)(((wm2 * 16 + l15) * 1032 + acol) * 2);
    uint32_t wB  = s32(Ws) + (uint32_t)(((wn2 * 16 + brow) * 72 + bcol) * 2);

    float c2[2][4];
#pragma unroll
    for (int a = 0; a < 2; a++)
#pragma unroll
        for (int k = 0; k < 4; k++) c2[a][k] = 0.f;

    // prefetch chunk 0 into buffer 0
#pragma unroll
    for (int it = 0; it < 2; it++) {
        int idx = tid + it * 512; int r = idx >> 3, c = (idx & 7) * 8;
        cp16(s32(Ws) + (r * 72 + c) * 2, g_Wt + r * 1024 + c);
    }
    CP_COMMIT();
    CP_WAIT0();
    __syncthreads();

    int buf = 0;
    for (int kc = 0; kc < 16; kc++) {
        if (kc < 15) {
            int nb = buf ^ 1;
#pragma unroll
            for (int it = 0; it < 2; it++) {
                int idx = tid + it * 512; int r = idx >> 3, c = (idx & 7) * 8;
                cp16(s32(Ws) + nb * 18432 + (r * 72 + c) * 2,
                     g_Wt + r * 1024 + (kc + 1) * 64 + c);
            }
            CP_COMMIT();
        }
#pragma unroll
        for (int ks = 0; ks < 4; ks++) {
            uint32_t a[4], b[4];
            ldsm4(a[0], a[1], a[2], a[3], a2B + (kc * 64 + ks * 16) * 2);
            ldsm4(b[0], b[1], b[2], b[3], wB + buf * 18432 + ks * 32);
            MMA_16816(c2[0], a, b);
            MMA_16816(c2[1], a, b + 2);
        }
        CP_WAIT0();
        __syncthreads();
        buf ^= 1;
    }

    // ---- phase-2 epilogue: (+bias) / (norm + 0.001) ----
    int lr0 = wm2 * 16 + g;
    int lr1 = lr0 + 8;
    int or0 = (bm * 4 + (lr0 >> 3)) * I_DIM + bn * 8 + (lr0 & 7);
    int or1 = (bm * 4 + (lr1 >> 3)) * I_DIM + bn * 8 + (lr1 & 7);
    float rn0 = 1.f / (g_norm[or0] + 0.001f);
    float rn1 = 1.f / (g_norm[or1] + 0.001f);
#pragma unroll
    for (int nf = 0; nf < 2; nf++) {
        int f = wn2 * 16 + nf * 8 + tg * 2;
        float2 bias = *(const float2*)&obias[f];
        float2 o0, o1;
        o0.x = (c2[nf][0] + bias.x) * rn0;
        o0.y = (c2[nf][1] + bias.y) * rn0;
        o1.x = (c2[nf][2] + bias.x) * rn1;
        o1.y = (c2[nf][3] + bias.y) * rn1;
        *(float2*)&out[(size_t)or0 * F_DIM + f] = o0;
        *(float2*)&out[(size_t)or1 * F_DIM + f] = o1;
    }
}

// ---------------- launch ---------------------------------------------------
extern "C" void kernel_launch(void* const* d_in, const int* in_sizes, int n_in,
                              void* d_out, int out_size) {
    (void)in_sizes; (void)n_in; (void)out_size;
    const float* node = (const float*)d_in[0];   // (128,384,256)
    const float* mask = (const float*)d_in[1];   // (128,384)
    const float* Wp   = (const float*)d_in[2];   // (256,64)
    const float* bp   = (const float*)d_in[3];   // (64,)
    const float* Wo   = (const float*)d_in[4];   // (32,32,128)
    const float* ob   = (const float*)d_in[5];   // (128,)
    float* out = (float*)d_out;                  // (384,384,128)

    static bool attr_set = false;
    if (!attr_set) {
        cudaFuncSetAttribute(k_fused, cudaFuncAttributeMaxDynamicSharedMemorySize,
                             SM_FUSED);
        attr_set = true;
    }

    k_ln_proj<<<S_DIM * I_DIM, 256>>>(node, mask, Wp, bp);
    k_wt<<<(F_DIM * 1024) / 256, 256>>>(Wo);
    k_norm<<<dim3(I_DIM / 16, I_DIM / 16), 256>>>(mask);
    k_fused<<<dim3(I_DIM / 4, I_DIM / 8), 512, SM_FUSED>>>(ob, out);
}

// round 6
// speedup vs baseline: 1.1713x; 1.1713x over previous
#include <cuda_runtime.h>
#include <cuda_fp16.h>
#include <cstdint>
#include <cstddef>

// Problem dims
#define S_DIM  128
#define I_DIM  384
#define INJ    256   // IN_DIM
#define PD     32    // PROJ_DIM
#define PD2    64
#define F_DIM  128   // OUT_DIM
#define MROWS  (I_DIM*PD)       // 12288

// ---------------- scratch (device globals; no allocation allowed) ----------
__device__ __align__(16) __half g_L[MROWS * S_DIM];   // [(i*32+d)][s]  3.1 MB
__device__ __align__(16) __half g_R[MROWS * S_DIM];   // [(j*32+e)][s]  3.1 MB
__device__ __align__(16) __half g_Wt[F_DIM * 1024];   // [f][(d*32+e)]  256 KB
__device__ __align__(16) __half g_G[(size_t)I_DIM * I_DIM * 1024]; // [i][j][d][e] 302 MB
__device__ float g_norm[I_DIM * I_DIM];

// ---------------- helpers --------------------------------------------------
__device__ __forceinline__ uint32_t s32(const void* p) {
    return (uint32_t)__cvta_generic_to_shared(p);
}
__device__ __forceinline__ void ldsm4(uint32_t& r0, uint32_t& r1, uint32_t& r2,
                                      uint32_t& r3, uint32_t a) {
    asm volatile("ldmatrix.sync.aligned.m8n8.x4.shared.b16 {%0,%1,%2,%3}, [%4];"
                 : "=r"(r0), "=r"(r1), "=r"(r2), "=r"(r3) : "r"(a));
}
__device__ __forceinline__ void cp16(uint32_t dst, const void* src) {
    asm volatile("cp.async.ca.shared.global [%0], [%1], 16;" :: "r"(dst), "l"(src));
}
#define CP_COMMIT() asm volatile("cp.async.commit_group;")
#define CP_WAIT0()  asm volatile("cp.async.wait_group 0;")

#define MMA_16816(C, A, B)                                                      \
    asm volatile("mma.sync.aligned.m16n8k16.row.col.f32.f16.f16.f32 "           \
                 "{%0,%1,%2,%3}, {%4,%5,%6,%7}, {%8,%9}, {%0,%1,%2,%3};"        \
                 : "+f"((C)[0]), "+f"((C)[1]), "+f"((C)[2]), "+f"((C)[3])       \
                 : "r"((A)[0]), "r"((A)[1]), "r"((A)[2]), "r"((A)[3]),          \
                   "r"((B)[0]), "r"((B)[1]))

// ---------------- K1: layernorm + projection + mask -> L,R (fp16 rn) -------
// 32 rows per block; W_proj staged once in 64KB dynamic smem.
__global__ __launch_bounds__(256) void k_ln_proj(const float* __restrict__ x,
                                                 const float* __restrict__ mask,
                                                 const float* __restrict__ Wp,
                                                 const float* __restrict__ bp) {
    extern __shared__ float Wps[];            // 16384 floats = 64 KB
    __shared__ float xs[INJ];
    __shared__ float red[16];
    __shared__ float pacc[256];

    int t = threadIdx.x;
#pragma unroll 8
    for (int it = 0; it < 64; it++) Wps[t + it * 256] = Wp[t + it * 256];
    __syncthreads();

    int c = t & 63, q = t >> 6;
    int k0 = q * 64;

    for (int rr = 0; rr < 32; rr++) {
        int row = blockIdx.x * 32 + rr;       // row = s*384 + i
        int s = row / I_DIM;
        int i = row - s * I_DIM;

        float v = x[(size_t)row * INJ + t];
        float sum = v, sq = v * v;
#pragma unroll
        for (int o = 16; o > 0; o >>= 1) {
            sum += __shfl_xor_sync(0xffffffffu, sum, o);
            sq  += __shfl_xor_sync(0xffffffffu, sq, o);
        }
        if ((t & 31) == 0) { red[t >> 5] = sum; red[8 + (t >> 5)] = sq; }
        __syncthreads();
        float ts = 0.f, tq = 0.f;
#pragma unroll
        for (int w = 0; w < 8; w++) { ts += red[w]; tq += red[8 + w]; }
        float mean = ts * (1.f / INJ);
        float var  = tq * (1.f / INJ) - mean * mean;
        float rstd = rsqrtf(var + 1e-5f);
        xs[t] = (v - mean) * rstd;
        __syncthreads();

        float acc = 0.f;
#pragma unroll 8
        for (int k = k0; k < k0 + 64; k++) acc += xs[k] * Wps[k * PD2 + c];
        pacc[t] = acc;
        __syncthreads();
        if (q == 0) {
            float tot = pacc[c] + pacc[c + 64] + pacc[c + 128] + pacc[c + 192] + bp[c];
            tot *= mask[row];
            __half h = __float2half_rn(tot);
            if (c < PD) g_L[((size_t)(i * PD + c)) * S_DIM + s] = h;
            else        g_R[((size_t)(i * PD + (c - PD))) * S_DIM + s] = h;
        }
        __syncthreads();
    }
}

// ---------------- K2: transpose out_weights -> Wt[f][d*32+e] (fp16 rn) -----
__global__ __launch_bounds__(256) void k_wt(const float* __restrict__ w) {
    int idx = blockIdx.x * 256 + threadIdx.x;   // idx = f*1024 + de
    int f  = idx >> 10;
    int de = idx & 1023;
    g_Wt[idx] = __float2half_rn(w[de * F_DIM + f]);
}

// ---------------- K3: norm[i][j] = sum_s mask[s][i]*mask[s][j] -------------
// 32x32 output tile per block, smem-staged mask columns, one barrier.
__global__ __launch_bounds__(256) void k_norm(const float* __restrict__ mask) {
    __shared__ float Mi[S_DIM][33];
    __shared__ float Mj[S_DIM][33];
    int t = threadIdx.x;
    int i0 = blockIdx.x * 32, j0 = blockIdx.y * 32;
#pragma unroll
    for (int it = 0; it < 16; it++) {
        int idx = t + it * 256;
        int s = idx >> 5, cc = idx & 31;
        Mi[s][cc] = mask[s * I_DIM + i0 + cc];
        Mj[s][cc] = mask[s * I_DIM + j0 + cc];
    }
    __syncthreads();
    int tx = t & 15, ty = t >> 4;
    float a00 = 0.f, a01 = 0.f, a10 = 0.f, a11 = 0.f;
#pragma unroll 4
    for (int s = 0; s < S_DIM; s++) {
        float mi0 = Mi[s][ty * 2], mi1 = Mi[s][ty * 2 + 1];
        float mj0 = Mj[s][tx * 2], mj1 = Mj[s][tx * 2 + 1];
        a00 += mi0 * mj0; a01 += mi0 * mj1;
        a10 += mi1 * mj0; a11 += mi1 * mj1;
    }
    int orow = (i0 + ty * 2) * I_DIM + j0 + tx * 2;
    g_norm[orow]             = a00;
    g_norm[orow + 1]         = a01;
    g_norm[orow + I_DIM]     = a10;
    g_norm[orow + I_DIM + 1] = a11;
}

// ---------------- K4: GEMM1  G[(i,d),(j,e)] = L * R^T, K = 128 -------------
// CTA 128x128, full K in smem (no k-loop), 8 warps (4x2) of 32x64, ldmatrix.
#define SM_G1 (2 * 128 * 136 * 2)   // 69632 B
__global__ __launch_bounds__(256, 2) void k_gemm1() {
    extern __shared__ __half sm1[];
    __half* As = sm1;                 // [128][136]
    __half* Bs = sm1 + 128 * 136;     // [128][136]

    int tid = threadIdx.x, lane = tid & 31, wid = tid >> 5;
    int wm = wid & 3, wn = wid >> 2;
    int g = lane >> 2, tg = lane & 3;
    int bm = blockIdx.x, bn = blockIdx.y;
    const __half* Ag = g_L + (size_t)bm * 128 * S_DIM;
    const __half* Bg = g_R + (size_t)bn * 128 * S_DIM;

#pragma unroll
    for (int it = 0; it < 8; it++) {
        int idx = tid + it * 256;
        int r = idx >> 4, cc = (idx & 15) * 8;
        *(uint4*)(As + r * 136 + cc) = *(const uint4*)(Ag + r * S_DIM + cc);
        *(uint4*)(Bs + r * 136 + cc) = *(const uint4*)(Bg + r * S_DIM + cc);
    }
    __syncthreads();

    int l15  = lane & 15;
    int acol = (lane >> 4) << 3;
    int brow = (lane & 7) + ((lane >> 4) << 3);
    int bcol = ((lane >> 3) & 1) << 3;
    uint32_t aB = s32(As) + (uint32_t)(((wm * 32 + l15) * 136 + acol) * 2);
    uint32_t bB = s32(Bs) + (uint32_t)(((wn * 64 + brow) * 136 + bcol) * 2);

    float c1[2][8][4];
#pragma unroll
    for (int a = 0; a < 2; a++)
#pragma unroll
        for (int b = 0; b < 8; b++)
#pragma unroll
            for (int k = 0; k < 4; k++) c1[a][b][k] = 0.f;

#pragma unroll
    for (int kk = 0; kk < 8; kk++) {
        uint32_t a[2][4], b[8][2];
        ldsm4(a[0][0], a[0][1], a[0][2], a[0][3], aB + kk * 32);
        ldsm4(a[1][0], a[1][1], a[1][2], a[1][3], aB + 16 * 136 * 2 + kk * 32);
#pragma unroll
        for (int p = 0; p < 4; p++)
            ldsm4(b[2 * p][0], b[2 * p][1], b[2 * p + 1][0], b[2 * p + 1][1],
                  bB + p * 16 * 136 * 2 + kk * 32);
#pragma unroll
        for (int mi = 0; mi < 2; mi++)
#pragma unroll
            for (int ni = 0; ni < 8; ni++)
                MMA_16816(c1[mi][ni], a[mi], b[ni]);
    }

    // Epilogue: scatter into G[i][j][d][e] as fp16(rn)
#pragma unroll
    for (int mi = 0; mi < 2; mi++) {
#pragma unroll
        for (int ni = 0; ni < 8; ni++) {
            int r0 = bm * 128 + wm * 32 + mi * 16 + g;
            int n0 = bn * 128 + wn * 64 + ni * 8 + tg * 2;
            int j = n0 >> 5, e = n0 & 31;
            {
                int ii = r0 >> 5, d = r0 & 31;
                *(__half2*)&g_G[(((size_t)ii * I_DIM + j) << 10) + (d << 5) + e] =
                    __floats2half2_rn(c1[mi][ni][0], c1[mi][ni][1]);
            }
            {
                int r1 = r0 + 8;
                int ii = r1 >> 5, d = r1 & 31;
                *(__half2*)&g_G[(((size_t)ii * I_DIM + j) << 10) + (d << 5) + e] =
                    __floats2half2_rn(c1[mi][ni][2], c1[mi][ni][3]);
            }
        }
    }
}

// ---------------- K5: GEMM2  out[(i,j),f] = G * Wt^T + bias, /(norm+1e-3) --
// M=147456, N=128, K=1024 in 16 chunks of 64; cp.async double-buffered; ldsm.
#define SM_G2 (4 * 128 * 72 * 2)    // 73728 B: As[2] then Bs[2], 18432 B each
__global__ __launch_bounds__(256, 2) void k_gemm2(const float* __restrict__ obias,
                                                  float* __restrict__ out) {
    extern __shared__ __half sm2[];
    __half* As = sm2;                  // 2 x [128][72]
    __half* Bs = sm2 + 2 * 128 * 72;   // 2 x [128][72]

    int tid = threadIdx.x, lane = tid & 31, wid = tid >> 5;
    int wm = wid & 3, wn = wid >> 2;
    int g = lane >> 2, tg = lane & 3;
    int bm = blockIdx.x;
    const __half* Ag = g_G + (size_t)bm * 128 * 1024;

    int l15  = lane & 15;
    int acol = (lane >> 4) << 3;
    int brow = (lane & 7) + ((lane >> 4) << 3);
    int bcol = ((lane >> 3) & 1) << 3;
    uint32_t asB = s32(As), bsB = s32(Bs);
    uint32_t aB = asB + (uint32_t)(((wm * 32 + l15) * 72 + acol) * 2);
    uint32_t bB = bsB + (uint32_t)(((wn * 64 + brow) * 72 + bcol) * 2);

    int lr = tid >> 3, lc = (tid & 7) * 8;     // load coords: 128 rows x 64 cols

    float c2[2][8][4];
#pragma unroll
    for (int a = 0; a < 2; a++)
#pragma unroll
        for (int b = 0; b < 8; b++)
#pragma unroll
            for (int k = 0; k < 4; k++) c2[a][b][k] = 0.f;

    // prefetch chunk 0 into buffer 0
#pragma unroll
    for (int h = 0; h < 4; h++) {
        int r = lr + (h & 1) * 32 + (h >> 1) * 64;
        cp16(asB + (uint32_t)((r * 72 + lc) * 2), Ag + (size_t)r * 1024 + lc);
        cp16(bsB + (uint32_t)((r * 72 + lc) * 2), g_Wt + (size_t)r * 1024 + lc);
    }
    CP_COMMIT();
    CP_WAIT0();
    __syncthreads();

    int buf = 0;
    for (int kc = 0; kc < 16; kc++) {
        if (kc < 15) {
            uint32_t off = (uint32_t)((buf ^ 1) * 18432);
            int kcol = (kc + 1) * 64;
#pragma unroll
            for (int h = 0; h < 4; h++) {
                int r = lr + (h & 1) * 32 + (h >> 1) * 64;
                cp16(asB + off + (uint32_t)((r * 72 + lc) * 2),
                     Ag + (size_t)r * 1024 + kcol + lc);
                cp16(bsB + off + (uint32_t)((r * 72 + lc) * 2),
                     g_Wt + (size_t)r * 1024 + kcol + lc);
            }
            CP_COMMIT();
        }
        uint32_t boff = (uint32_t)(buf * 18432);
#pragma unroll
        for (int kk = 0; kk < 4; kk++) {
            uint32_t a[2][4], b[8][2];
            ldsm4(a[0][0], a[0][1], a[0][2], a[0][3], aB + boff + kk * 32);
            ldsm4(a[1][0], a[1][1], a[1][2], a[1][3], aB + boff + 16 * 72 * 2 + kk * 32);
#pragma unroll
            for (int p = 0; p < 4; p++)
                ldsm4(b[2 * p][0], b[2 * p][1], b[2 * p + 1][0], b[2 * p + 1][1],
                      bB + boff + p * 16 * 72 * 2 + kk * 32);
#pragma unroll
            for (int mi = 0; mi < 2; mi++)
#pragma unroll
                for (int ni = 0; ni < 8; ni++)
                    MMA_16816(c2[mi][ni], a[mi], b[ni]);
        }
        CP_WAIT0();
        __syncthreads();
        buf ^= 1;
    }

    // Epilogue: (+bias) / (norm + 0.001)
#pragma unroll
    for (int mi = 0; mi < 2; mi++) {
        int p0 = bm * 128 + wm * 32 + mi * 16 + g;
        float rn0 = 1.f / (g_norm[p0] + 0.001f);
        float rn1 = 1.f / (g_norm[p0 + 8] + 0.001f);
#pragma unroll
        for (int ni = 0; ni < 8; ni++) {
            int f = wn * 64 + ni * 8 + tg * 2;
            float2 bias = *(const float2*)&obias[f];
            float2 o0, o1;
            o0.x = (c2[mi][ni][0] + bias.x) * rn0;
            o0.y = (c2[mi][ni][1] + bias.y) * rn0;
            o1.x = (c2[mi][ni][2] + bias.x) * rn1;
            o1.y = (c2[mi][ni][3] + bias.y) * rn1;
            *(float2*)&out[(size_t)p0 * F_DIM + f] = o0;
            *(float2*)&out[(size_t)(p0 + 8) * F_DIM + f] = o1;
        }
    }
}

// ---------------- launch ---------------------------------------------------
extern "C" void kernel_launch(void* const* d_in, const int* in_sizes, int n_in,
                              void* d_out, int out_size) {
    (void)in_sizes; (void)n_in; (void)out_size;
    const float* node = (const float*)d_in[0];   // (128,384,256)
    const float* mask = (const float*)d_in[1];   // (128,384)
    const float* Wp   = (const float*)d_in[2];   // (256,64)
    const float* bp   = (const float*)d_in[3];   // (64,)
    const float* Wo   = (const float*)d_in[4];   // (32,32,128)
    const float* ob   = (const float*)d_in[5];   // (128,)
    float* out = (float*)d_out;                  // (384,384,128)

    static bool attr_set = false;
    if (!attr_set) {
        cudaFuncSetAttribute(k_ln_proj, cudaFuncAttributeMaxDynamicSharedMemorySize,
                             65536);
        cudaFuncSetAttribute(k_gemm1, cudaFuncAttributeMaxDynamicSharedMemorySize,
                             SM_G1);
        cudaFuncSetAttribute(k_gemm2, cudaFuncAttributeMaxDynamicSharedMemorySize,
                             SM_G2);
        attr_set = true;
    }

    k_ln_proj<<<S_DIM * I_DIM / 32, 256, 65536>>>(node, mask, Wp, bp);
    k_wt<<<(F_DIM * 1024) / 256, 256>>>(Wo);
    k_norm<<<dim3(I_DIM / 32, I_DIM / 32), 256>>>(mask);
    k_gemm1<<<dim3(MROWS / 128, MROWS / 128), 256, SM_G1>>>();
    k_gemm2<<<(I_DIM * I_DIM) / 128, 256, SM_G2>>>(ob, out);
}

// round 7
// speedup vs baseline: 1.4290x; 1.2200x over previous
#include <cuda_runtime.h>
#include <cuda_fp16.h>
#include <cstdint>
#include <cstddef>

// Problem dims
#define S_DIM  128
#define I_DIM  384
#define INJ    256   // IN_DIM
#define PD     32    // PROJ_DIM
#define PD2    64
#define F_DIM  128   // OUT_DIM
#define MROWS  (I_DIM*PD)       // 12288

// ---------------- scratch (device globals; no allocation allowed) ----------
__device__ __align__(16) __half g_L[MROWS * S_DIM];   // [(i*32+d)][s]  3.1 MB
__device__ __align__(16) __half g_R[MROWS * S_DIM];   // [(j*32+e)][s]  3.1 MB
__device__ __align__(16) __half g_Wt[F_DIM * 1024];   // [f][(d*32+e)]  256 KB
__device__ __align__(16) __half g_G[(size_t)I_DIM * I_DIM * 1024]; // [i][j][d][e] 302 MB
__device__ float g_norm[I_DIM * I_DIM];

// ---------------- helpers --------------------------------------------------
__device__ __forceinline__ uint32_t s32(const void* p) {
    return (uint32_t)__cvta_generic_to_shared(p);
}
__device__ __forceinline__ void ldsm4(uint32_t& r0, uint32_t& r1, uint32_t& r2,
                                      uint32_t& r3, uint32_t a) {
    asm volatile("ldmatrix.sync.aligned.m8n8.x4.shared.b16 {%0,%1,%2,%3}, [%4];"
                 : "=r"(r0), "=r"(r1), "=r"(r2), "=r"(r3) : "r"(a));
}
__device__ __forceinline__ void stsm4(uint32_t a, uint32_t r0, uint32_t r1,
                                      uint32_t r2, uint32_t r3) {
    asm volatile("stmatrix.sync.aligned.m8n8.x4.shared.b16 [%0], {%1,%2,%3,%4};"
                 :: "r"(a), "r"(r0), "r"(r1), "r"(r2), "r"(r3));
}
__device__ __forceinline__ void cp16(uint32_t dst, const void* src) {
    asm volatile("cp.async.ca.shared.global [%0], [%1], 16;" :: "r"(dst), "l"(src));
}
#define CP_COMMIT() asm volatile("cp.async.commit_group;")
#define CP_WAIT0()  asm volatile("cp.async.wait_group 0;")
#define CP_WAIT1()  asm volatile("cp.async.wait_group 1;")

#define MMA_16816(C, A, B)                                                      \
    asm volatile("mma.sync.aligned.m16n8k16.row.col.f32.f16.f16.f32 "           \
                 "{%0,%1,%2,%3}, {%4,%5,%6,%7}, {%8,%9}, {%0,%1,%2,%3};"        \
                 : "+f"((C)[0]), "+f"((C)[1]), "+f"((C)[2]), "+f"((C)[3])       \
                 : "r"((A)[0]), "r"((A)[1]), "r"((A)[2]), "r"((A)[3]),          \
                   "r"((B)[0]), "r"((B)[1]))

// ---------------- K1: layernorm + projection + mask -> L,R (fp16 rn) -------
// One warp per row (8 rows/warp serially), W_proj staged once in smem.
// No block barriers after staging. Dyn smem = 64KB W + 8KB xrows = 73728 B.
__global__ __launch_bounds__(256) void k_ln_proj(const float* __restrict__ x,
                                                 const float* __restrict__ mask,
                                                 const float* __restrict__ Wp,
                                                 const float* __restrict__ bp) {
    extern __shared__ float Wps[];            // [256][64]
    float* xr = Wps + 16384;                  // 8 warps x 256

    int t = threadIdx.x, lane = t & 31, w = t >> 5;
#pragma unroll 8
    for (int it = 0; it < 64; it++) Wps[t + it * 256] = Wp[t + it * 256];
    __syncthreads();

    float* xs = xr + w * 256;
    int q = lane >> 3, p = lane & 7;
    int k0 = q * 64;

    for (int rr = 0; rr < 8; rr++) {
        int row = blockIdx.x * 64 + w * 8 + rr;   // row = s*384 + i
        int s = row / I_DIM;
        int i = row - s * I_DIM;

        float v[8];
        float sum = 0.f, sq = 0.f;
#pragma unroll
        for (int k8 = 0; k8 < 8; k8++) {
            v[k8] = x[(size_t)row * INJ + lane + k8 * 32];
            sum += v[k8]; sq += v[k8] * v[k8];
        }
#pragma unroll
        for (int o = 16; o > 0; o >>= 1) {
            sum += __shfl_xor_sync(0xffffffffu, sum, o);
            sq  += __shfl_xor_sync(0xffffffffu, sq, o);
        }
        float mean = sum * (1.f / INJ);
        float var  = sq * (1.f / INJ) - mean * mean;
        float rstd = rsqrtf(var + 1e-5f);
#pragma unroll
        for (int k8 = 0; k8 < 8; k8++)
            xs[lane + k8 * 32] = (v[k8] - mean) * rstd;
        __syncwarp();

        // thread (q,p): k-range [q*64, q*64+64), cols {p*4..p*4+3, 32+p*4..+3}
        float acc[8];
#pragma unroll
        for (int cc = 0; cc < 8; cc++) acc[cc] = 0.f;
#pragma unroll 4
        for (int k = k0; k < k0 + 64; k++) {
            float xv = xs[k];
            float4 w0 = *(const float4*)&Wps[k * PD2 + p * 4];
            float4 w1 = *(const float4*)&Wps[k * PD2 + 32 + p * 4];
            acc[0] += xv * w0.x; acc[1] += xv * w0.y;
            acc[2] += xv * w0.z; acc[3] += xv * w0.w;
            acc[4] += xv * w1.x; acc[5] += xv * w1.y;
            acc[6] += xv * w1.z; acc[7] += xv * w1.w;
        }
#pragma unroll
        for (int cc = 0; cc < 8; cc++) {
            acc[cc] += __shfl_xor_sync(0xffffffffu, acc[cc], 8);
            acc[cc] += __shfl_xor_sync(0xffffffffu, acc[cc], 16);
        }
        if (lane < 8) {
            float m = mask[row];
#pragma unroll
            for (int cc = 0; cc < 4; cc++) {
                int ca = p * 4 + cc;               // L col (0..31)
                float ta = (acc[cc] + bp[ca]) * m;
                g_L[((size_t)(i * PD + ca)) * S_DIM + s] = __float2half_rn(ta);
                float tb = (acc[4 + cc] + bp[32 + ca]) * m;
                g_R[((size_t)(i * PD + ca)) * S_DIM + s] = __float2half_rn(tb);
            }
        }
        __syncwarp();
    }
}

// ---------------- K2: transpose out_weights -> Wt[f][d*32+e] (fp16 rn) -----
__global__ __launch_bounds__(256) void k_wt(const float* __restrict__ w) {
    int idx = blockIdx.x * 256 + threadIdx.x;   // idx = f*1024 + de
    int f  = idx >> 10;
    int de = idx & 1023;
    g_Wt[idx] = __float2half_rn(w[de * F_DIM + f]);
}

// ---------------- K3: norm[i][j] = sum_s mask[s][i]*mask[s][j] -------------
__global__ __launch_bounds__(256) void k_norm(const float* __restrict__ mask) {
    __shared__ float Mi[S_DIM][33];
    __shared__ float Mj[S_DIM][33];
    int t = threadIdx.x;
    int i0 = blockIdx.x * 32, j0 = blockIdx.y * 32;
#pragma unroll
    for (int it = 0; it < 16; it++) {
        int idx = t + it * 256;
        int s = idx >> 5, cc = idx & 31;
        Mi[s][cc] = mask[s * I_DIM + i0 + cc];
        Mj[s][cc] = mask[s * I_DIM + j0 + cc];
    }
    __syncthreads();
    int tx = t & 15, ty = t >> 4;
    float a00 = 0.f, a01 = 0.f, a10 = 0.f, a11 = 0.f;
#pragma unroll 4
    for (int s = 0; s < S_DIM; s++) {
        float mi0 = Mi[s][ty * 2], mi1 = Mi[s][ty * 2 + 1];
        float mj0 = Mj[s][tx * 2], mj1 = Mj[s][tx * 2 + 1];
        a00 += mi0 * mj0; a01 += mi0 * mj1;
        a10 += mi1 * mj0; a11 += mi1 * mj1;
    }
    int orow = (i0 + ty * 2) * I_DIM + j0 + tx * 2;
    g_norm[orow]             = a00;
    g_norm[orow + 1]         = a01;
    g_norm[orow + I_DIM]     = a10;
    g_norm[orow + I_DIM + 1] = a11;
}

// ---------------- K4: GEMM1 persistent  G[(i,d),(j,e)] = L * R^T -----------
// Tiles 96x96 of 128x128, K=128. Grid = 152 persistent CTAs, 512 threads
// (16 warps 4x4, warp 32x32). cp.async double-buffers the NEXT tile during
// the current tile's MMA. Epilogue: stmatrix -> per-warp smem stage ->
// coalesced STG.128 (each warp's output = one contiguous 2KB G block).
// Dyn smem: 2 x (A[128][136] + B[128][136]) = 139264  +  16 x 32 x 40 halfs
// stage = 40960  -> total 180224 B.
#define G1_BUF   69632
#define G1_STAGE 139264
#define SM_G1P   180224
#define NT1      (96 * 96)

__global__ __launch_bounds__(512, 1) void k_gemm1() {
    extern __shared__ char sm_[];
    uint32_t smA = s32(sm_);
    uint32_t smB = smA + 34816;

    int tid = threadIdx.x, lane = tid & 31, wid = tid >> 5;
    int wm = wid & 3, wn = wid >> 2;
    int g = lane >> 2, tg = lane & 3;
    int l15  = lane & 15;
    int acol = (lane >> 4) << 3;
    int brow = (lane & 7) + ((lane >> 4) << 3);
    int bcol = ((lane >> 3) & 1) << 3;

    __half* stage = (__half*)(sm_ + G1_STAGE) + wid * (32 * 40);
    uint32_t stS = s32(stage);

    // loader lambda: tile t -> buffer b
    auto issue = [&](int t, int b) {
        int tm = t / 96, tn = t - tm * 96;
        const __half* Ag = g_L + (size_t)tm * 128 * S_DIM;
        const __half* Bg = g_R + (size_t)tn * 128 * S_DIM;
        uint32_t aD = smA + (uint32_t)b * G1_BUF;
        uint32_t bD = smB + (uint32_t)b * G1_BUF;
#pragma unroll
        for (int it = 0; it < 4; it++) {
            int idx = tid + it * 512;
            int r = idx >> 4, c = (idx & 15) * 8;
            cp16(aD + (uint32_t)((r * 136 + c) * 2), Ag + r * S_DIM + c);
            cp16(bD + (uint32_t)((r * 136 + c) * 2), Bg + r * S_DIM + c);
        }
        CP_COMMIT();
    };

    int t0 = blockIdx.x;
    if (t0 < NT1) issue(t0, 0);

    int buf = 0;
    for (int t = t0; t < NT1; t += gridDim.x) {
        int tnx = t + gridDim.x;
        bool has_next = (tnx < NT1);
        if (has_next) issue(tnx, buf ^ 1);
        if (has_next) { CP_WAIT1(); } else { CP_WAIT0(); }
        __syncthreads();

        uint32_t aB = smA + (uint32_t)buf * G1_BUF +
                      (uint32_t)(((wm * 32 + l15) * 136 + acol) * 2);
        uint32_t bB = smB + (uint32_t)buf * G1_BUF +
                      (uint32_t)(((wn * 32 + brow) * 136 + bcol) * 2);

        float c1[2][4][4];
#pragma unroll
        for (int a = 0; a < 2; a++)
#pragma unroll
            for (int b = 0; b < 4; b++)
#pragma unroll
                for (int k = 0; k < 4; k++) c1[a][b][k] = 0.f;

#pragma unroll
        for (int kk = 0; kk < 8; kk++) {
            uint32_t a[2][4], b[4][2];
            ldsm4(a[0][0], a[0][1], a[0][2], a[0][3], aB + kk * 32);
            ldsm4(a[1][0], a[1][1], a[1][2], a[1][3], aB + 16 * 136 * 2 + kk * 32);
#pragma unroll
            for (int p = 0; p < 2; p++)
                ldsm4(b[2 * p][0], b[2 * p][1], b[2 * p + 1][0], b[2 * p + 1][1],
                      bB + p * 16 * 136 * 2 + kk * 32);
#pragma unroll
            for (int mi = 0; mi < 2; mi++)
#pragma unroll
                for (int ni = 0; ni < 4; ni++)
                    MMA_16816(c1[mi][ni], a[mi], b[ni]);
        }

        // epilogue: fragments -> fp16 stage via stmatrix, then coalesced STG
        int tm = t / 96, tn = t - tm * 96;
#pragma unroll
        for (int mi = 0; mi < 2; mi++) {
#pragma unroll
            for (int h = 0; h < 2; h++) {
                uint32_t r[4];
#pragma unroll
                for (int nb = 0; nb < 4; nb++) {
                    __half2 hv = __floats2half2_rn(c1[mi][nb][2 * h],
                                                   c1[mi][nb][2 * h + 1]);
                    r[nb] = *(uint32_t*)&hv;
                }
                uint32_t ad = stS + (uint32_t)(((mi * 16 + h * 8 + (lane & 7)) * 40 +
                                                (lane >> 3) * 8) * 2);
                stsm4(ad, r[0], r[1], r[2], r[3]);
            }
        }
        __syncwarp();
        {
            int i_ = tm * 4 + wm, j_ = tn * 4 + wn;
            char* gb = (char*)(g_G + (((size_t)i_ * I_DIM + j_) << 10));
#pragma unroll
            for (int it = 0; it < 4; it++) {
                int o = it * 512 + lane * 16;         // byte offset in 2KB block
                int d = o >> 6, cb = o & 63;
                uint4 v = *(uint4*)((char*)stage + d * 80 + cb);
                *(uint4*)(gb + o) = v;
            }
        }
        __syncthreads();
        buf ^= 1;
    }
}

// ---------------- K5: GEMM2  out[(i,j),f] = G * Wt^T + bias, /(norm+1e-3) --
// M=147456, N=128, K=1024 in 16 chunks of 64; cp.async double-buffered; ldsm.
#define SM_G2 (4 * 128 * 72 * 2)    // 73728 B: As[2] then Bs[2], 18432 B each
__global__ __launch_bounds__(256, 2) void k_gemm2(const float* __restrict__ obias,
                                                  float* __restrict__ out) {
    extern __shared__ __half sm2[];
    __half* As = sm2;                  // 2 x [128][72]
    __half* Bs = sm2 + 2 * 128 * 72;   // 2 x [128][72]

    int tid = threadIdx.x, lane = tid & 31, wid = tid >> 5;
    int wm = wid & 3, wn = wid >> 2;
    int g = lane >> 2, tg = lane & 3;
    int bm = blockIdx.x;
    const __half* Ag = g_G + (size_t)bm * 128 * 1024;

    int l15  = lane & 15;
    int acol = (lane >> 4) << 3;
    int brow = (lane & 7) + ((lane >> 4) << 3);
    int bcol = ((lane >> 3) & 1) << 3;
    uint32_t asB = s32(As), bsB = s32(Bs);
    uint32_t aB = asB + (uint32_t)(((wm * 32 + l15) * 72 + acol) * 2);
    uint32_t bB = bsB + (uint32_t)(((wn * 64 + brow) * 72 + bcol) * 2);

    int lr = tid >> 3, lc = (tid & 7) * 8;

    float c2[2][8][4];
#pragma unroll
    for (int a = 0; a < 2; a++)
#pragma unroll
        for (int b = 0; b < 8; b++)
#pragma unroll
            for (int k = 0; k < 4; k++) c2[a][b][k] = 0.f;

#pragma unroll
    for (int h = 0; h < 4; h++) {
        int r = lr + (h & 1) * 32 + (h >> 1) * 64;
        cp16(asB + (uint32_t)((r * 72 + lc) * 2), Ag + (size_t)r * 1024 + lc);
        cp16(bsB + (uint32_t)((r * 72 + lc) * 2), g_Wt + (size_t)r * 1024 + lc);
    }
    CP_COMMIT();
    CP_WAIT0();
    __syncthreads();

    int buf = 0;
    for (int kc = 0; kc < 16; kc++) {
        if (kc < 15) {
            uint32_t off = (uint32_t)((buf ^ 1) * 18432);
            int kcol = (kc + 1) * 64;
#pragma unroll
            for (int h = 0; h < 4; h++) {
                int r = lr + (h & 1) * 32 + (h >> 1) * 64;
                cp16(asB + off + (uint32_t)((r * 72 + lc) * 2),
                     Ag + (size_t)r * 1024 + kcol + lc);
                cp16(bsB + off + (uint32_t)((r * 72 + lc) * 2),
                     g_Wt + (size_t)r * 1024 + kcol + lc);
            }
            CP_COMMIT();
        }
        uint32_t boff = (uint32_t)(buf * 18432);
#pragma unroll
        for (int kk = 0; kk < 4; kk++) {
            uint32_t a[2][4], b[8][2];
            ldsm4(a[0][0], a[0][1], a[0][2], a[0][3], aB + boff + kk * 32);
            ldsm4(a[1][0], a[1][1], a[1][2], a[1][3], aB + boff + 16 * 72 * 2 + kk * 32);
#pragma unroll
            for (int p = 0; p < 4; p++)
                ldsm4(b[2 * p][0], b[2 * p][1], b[2 * p + 1][0], b[2 * p + 1][1],
                      bB + boff + p * 16 * 72 * 2 + kk * 32);
#pragma unroll
            for (int mi = 0; mi < 2; mi++)
#pragma unroll
                for (int ni = 0; ni < 8; ni++)
                    MMA_16816(c2[mi][ni], a[mi], b[ni]);
        }
        CP_WAIT0();
        __syncthreads();
        buf ^= 1;
    }

#pragma unroll
    for (int mi = 0; mi < 2; mi++) {
        int p0 = bm * 128 + wm * 32 + mi * 16 + g;
        float rn0 = 1.f / (g_norm[p0] + 0.001f);
        float rn1 = 1.f / (g_norm[p0 + 8] + 0.001f);
#pragma unroll
        for (int ni = 0; ni < 8; ni++) {
            int f = wn * 64 + ni * 8 + tg * 2;
            float2 bias = *(const float2*)&obias[f];
            float2 o0, o1;
            o0.x = (c2[mi][ni][0] + bias.x) * rn0;
            o0.y = (c2[mi][ni][1] + bias.y) * rn0;
            o1.x = (c2[mi][ni][2] + bias.x) * rn1;
            o1.y = (c2[mi][ni][3] + bias.y) * rn1;
            *(float2*)&out[(size_t)p0 * F_DIM + f] = o0;
            *(float2*)&out[(size_t)(p0 + 8) * F_DIM + f] = o1;
        }
    }
}

// ---------------- launch ---------------------------------------------------
extern "C" void kernel_launch(void* const* d_in, const int* in_sizes, int n_in,
                              void* d_out, int out_size) {
    (void)in_sizes; (void)n_in; (void)out_size;
    const float* node = (const float*)d_in[0];   // (128,384,256)
    const float* mask = (const float*)d_in[1];   // (128,384)
    const float* Wp   = (const float*)d_in[2];   // (256,64)
    const float* bp   = (const float*)d_in[3];   // (64,)
    const float* Wo   = (const float*)d_in[4];   // (32,32,128)
    const float* ob   = (const float*)d_in[5];   // (128,)
    float* out = (float*)d_out;                  // (384,384,128)

    static bool attr_set = false;
    if (!attr_set) {
        cudaFuncSetAttribute(k_ln_proj, cudaFuncAttributeMaxDynamicSharedMemorySize,
                             73728);
        cudaFuncSetAttribute(k_gemm1, cudaFuncAttributeMaxDynamicSharedMemorySize,
                             SM_G1P);
        cudaFuncSetAttribute(k_gemm2, cudaFuncAttributeMaxDynamicSharedMemorySize,
                             SM_G2);
        attr_set = true;
    }

    k_ln_proj<<<S_DIM * I_DIM / 64, 256, 73728>>>(node, mask, Wp, bp);
    k_wt<<<(F_DIM * 1024) / 256, 256>>>(Wo);
    k_norm<<<dim3(I_DIM / 32, I_DIM / 32), 256>>>(mask);
    k_gemm1<<<152, 512, SM_G1P>>>();
    k_gemm2<<<(I_DIM * I_DIM) / 128, 256, SM_G2>>>(ob, out);
}

// round 15
// speedup vs baseline: 1.5180x; 1.0623x over previous
#include <cuda_runtime.h>
#include <cuda_fp16.h>
#include <cstdint>
#include <cstddef>

// Problem dims
#define S_DIM  128
#define I_DIM  384
#define INJ    256   // IN_DIM
#define PD     32    // PROJ_DIM
#define PD2    64
#define F_DIM  128   // OUT_DIM
#define MROWS  (I_DIM*PD)       // 12288

// ---------------- scratch (device globals; no allocation allowed) ----------
__device__ __align__(16) __half g_L[MROWS * S_DIM];   // [(i*32+d)][s]  3.1 MB
__device__ __align__(16) __half g_R[MROWS * S_DIM];   // [(j*32+e)][s]  3.1 MB
__device__ __align__(16) __half g_Wt[F_DIM * 1024];   // [f][(d*32+e)]  256 KB
__device__ __align__(16) __half g_G[(size_t)I_DIM * I_DIM * 1024]; // [i][j][d][e] 302 MB
__device__ float g_norm[I_DIM * I_DIM];

// ---------------- helpers --------------------------------------------------
__device__ __forceinline__ uint32_t s32(const void* p) {
    return (uint32_t)__cvta_generic_to_shared(p);
}
__device__ __forceinline__ void ldsm4(uint32_t& r0, uint32_t& r1, uint32_t& r2,
                                      uint32_t& r3, uint32_t a) {
    asm volatile("ldmatrix.sync.aligned.m8n8.x4.shared.b16 {%0,%1,%2,%3}, [%4];"
                 : "=r"(r0), "=r"(r1), "=r"(r2), "=r"(r3) : "r"(a));
}
__device__ __forceinline__ void stsm4(uint32_t a, uint32_t r0, uint32_t r1,
                                      uint32_t r2, uint32_t r3) {
    asm volatile("stmatrix.sync.aligned.m8n8.x4.shared.b16 [%0], {%1,%2,%3,%4};"
                 :: "r"(a), "r"(r0), "r"(r1), "r"(r2), "r"(r3));
}
__device__ __forceinline__ void cp16(uint32_t dst, const void* src) {
    asm volatile("cp.async.ca.shared.global [%0], [%1], 16;" :: "r"(dst), "l"(src));
}
#define CP_COMMIT() asm volatile("cp.async.commit_group;")
#define CP_WAIT0()  asm volatile("cp.async.wait_group 0;")
#define CP_WAIT1()  asm volatile("cp.async.wait_group 1;")

#define MMA_16816(C, A, B)                                                      \
    asm volatile("mma.sync.aligned.m16n8k16.row.col.f32.f16.f16.f32 "           \
                 "{%0,%1,%2,%3}, {%4,%5,%6,%7}, {%8,%9}, {%0,%1,%2,%3};"        \
                 : "+f"((C)[0]), "+f"((C)[1]), "+f"((C)[2]), "+f"((C)[3])       \
                 : "r"((A)[0]), "r"((A)[1]), "r"((A)[2]), "r"((A)[3]),          \
                   "r"((B)[0]), "r"((B)[1]))

// ---------------- K1: layernorm + projection + mask -> L,R (fp16 rn) -------
__global__ __launch_bounds__(256) void k_ln_proj(const float* __restrict__ x,
                                                 const float* __restrict__ mask,
                                                 const float* __restrict__ Wp,
                                                 const float* __restrict__ bp) {
    extern __shared__ float Wps[];            // [256][64]
    float* xr = Wps + 16384;                  // 8 warps x 256

    int t = threadIdx.x, lane = t & 31, w = t >> 5;
#pragma unroll 8
    for (int it = 0; it < 64; it++) Wps[t + it * 256] = Wp[t + it * 256];
    __syncthreads();

    float* xs = xr + w * 256;
    int q = lane >> 3, p = lane & 7;
    int k0 = q * 64;

    for (int rr = 0; rr < 8; rr++) {
        int row = blockIdx.x * 64 + w * 8 + rr;   // row = s*384 + i
        int s = row / I_DIM;
        int i = row - s * I_DIM;

        float v[8];
        float sum = 0.f, sq = 0.f;
#pragma unroll
        for (int k8 = 0; k8 < 8; k8++) {
            v[k8] = x[(size_t)row * INJ + lane + k8 * 32];
            sum += v[k8]; sq += v[k8] * v[k8];
        }
#pragma unroll
        for (int o = 16; o > 0; o >>= 1) {
            sum += __shfl_xor_sync(0xffffffffu, sum, o);
            sq  += __shfl_xor_sync(0xffffffffu, sq, o);
        }
        float mean = sum * (1.f / INJ);
        float var  = sq * (1.f / INJ) - mean * mean;
        float rstd = rsqrtf(var + 1e-5f);
#pragma unroll
        for (int k8 = 0; k8 < 8; k8++)
            xs[lane + k8 * 32] = (v[k8] - mean) * rstd;
        __syncwarp();

        float acc[8];
#pragma unroll
        for (int cc = 0; cc < 8; cc++) acc[cc] = 0.f;
#pragma unroll 4
        for (int k = k0; k < k0 + 64; k++) {
            float xv = xs[k];
            float4 w0 = *(const float4*)&Wps[k * PD2 + p * 4];
            float4 w1 = *(const float4*)&Wps[k * PD2 + 32 + p * 4];
            acc[0] += xv * w0.x; acc[1] += xv * w0.y;
            acc[2] += xv * w0.z; acc[3] += xv * w0.w;
            acc[4] += xv * w1.x; acc[5] += xv * w1.y;
            acc[6] += xv * w1.z; acc[7] += xv * w1.w;
        }
#pragma unroll
        for (int cc = 0; cc < 8; cc++) {
            acc[cc] += __shfl_xor_sync(0xffffffffu, acc[cc], 8);
            acc[cc] += __shfl_xor_sync(0xffffffffu, acc[cc], 16);
        }
        if (lane < 8) {
            float m = mask[row];
#pragma unroll
            for (int cc = 0; cc < 4; cc++) {
                int ca = p * 4 + cc;
                float ta = (acc[cc] + bp[ca]) * m;
                g_L[((size_t)(i * PD + ca)) * S_DIM + s] = __float2half_rn(ta);
                float tb = (acc[4 + cc] + bp[32 + ca]) * m;
                g_R[((size_t)(i * PD + ca)) * S_DIM + s] = __float2half_rn(tb);
            }
        }
        __syncwarp();
    }
}

// ---------------- K2: transpose out_weights -> Wt[f][d*32+e] (fp16 rn) -----
__global__ __launch_bounds__(256) void k_wt(const float* __restrict__ w) {
    int idx = blockIdx.x * 256 + threadIdx.x;
    int f  = idx >> 10;
    int de = idx & 1023;
    g_Wt[idx] = __float2half_rn(w[de * F_DIM + f]);
}

// ---------------- K3: norm[i][j] = sum_s mask[s][i]*mask[s][j] -------------
__global__ __launch_bounds__(256) void k_norm(const float* __restrict__ mask) {
    __shared__ float Mi[S_DIM][33];
    __shared__ float Mj[S_DIM][33];
    int t = threadIdx.x;
    int i0 = blockIdx.x * 32, j0 = blockIdx.y * 32;
#pragma unroll
    for (int it = 0; it < 16; it++) {
        int idx = t + it * 256;
        int s = idx >> 5, cc = idx & 31;
        Mi[s][cc] = mask[s * I_DIM + i0 + cc];
        Mj[s][cc] = mask[s * I_DIM + j0 + cc];
    }
    __syncthreads();
    int tx = t & 15, ty = t >> 4;
    float a00 = 0.f, a01 = 0.f, a10 = 0.f, a11 = 0.f;
#pragma unroll 4
    for (int s = 0; s < S_DIM; s++) {
        float mi0 = Mi[s][ty * 2], mi1 = Mi[s][ty * 2 + 1];
        float mj0 = Mj[s][tx * 2], mj1 = Mj[s][tx * 2 + 1];
        a00 += mi0 * mj0; a01 += mi0 * mj1;
        a10 += mi1 * mj0; a11 += mi1 * mj1;
    }
    int orow = (i0 + ty * 2) * I_DIM + j0 + tx * 2;
    g_norm[orow]             = a00;
    g_norm[orow + 1]         = a01;
    g_norm[orow + I_DIM]     = a10;
    g_norm[orow + I_DIM + 1] = a11;
}

// ---------------- K4: GEMM1 persistent  G[(i,d),(j,e)] = L * R^T -----------
// CTA tile 128(M) x 256(N), K=128 full. 96x48 = 4608 tiles, 152 persistent
// CTAs, 256 threads = 8 warps (wm 0..1, wn 0..3), warp tile 64x64.
// Smem: As0@0(34816) Bs0@34816(69632) As1@104448 Bs1@139264 stage@208896
// (8 x 2560) -> 229376 B.
#define G1_ABUF  104448
#define SM_G1    229376
#define NT1      (96 * 48)

__global__ __launch_bounds__(256, 1) void k_gemm1() {
    extern __shared__ char sm_[];
    uint32_t smA = s32(sm_);                  // + buf*G1_ABUF
    uint32_t smB = smA + 34816;

    int tid = threadIdx.x, lane = tid & 31, wid = tid >> 5;
    int wm = wid & 1, wn = wid >> 1;          // 2 x 4 warp grid
    int l15  = lane & 15;
    int acol = (lane >> 4) << 3;
    int brow = (lane & 7) + ((lane >> 4) << 3);
    int bcol = ((lane >> 3) & 1) << 3;

    char* stage = sm_ + 208896 + wid * 2560;  // 32 x 40 halfs per warp
    uint32_t stS = s32(stage);

    auto issue = [&](int t, int b) {
        int tm = t / 48, tn = t - tm * 48;
        const __half* Ag = g_L + (size_t)tm * 128 * S_DIM;
        const __half* Bg = g_R + (size_t)tn * 256 * S_DIM;
        uint32_t aD = smA + (uint32_t)b * G1_ABUF;
        uint32_t bD = smB + (uint32_t)b * G1_ABUF;
#pragma unroll
        for (int it = 0; it < 8; it++) {       // A: 128 rows x 16 uint4
            int idx = tid + it * 256;
            int r = idx >> 4, c = (idx & 15) * 8;
            cp16(aD + (uint32_t)((r * 136 + c) * 2), Ag + r * S_DIM + c);
        }
#pragma unroll
        for (int it = 0; it < 16; it++) {      // B: 256 rows x 16 uint4
            int idx = tid + it * 256;
            int r = idx >> 4, c = (idx & 15) * 8;
            cp16(bD + (uint32_t)((r * 136 + c) * 2), Bg + r * S_DIM + c);
        }
        CP_COMMIT();
    };

    int t0 = blockIdx.x;
    if (t0 < NT1) issue(t0, 0);

    int buf = 0;
    for (int t = t0; t < NT1; t += gridDim.x) {
        int nx = t + gridDim.x;
        bool has_next = (nx < NT1);
        if (has_next) issue(nx, buf ^ 1);
        // outstanding: {G_t (older), G_nx (newer)} -> WAIT1 drains G_t
        if (has_next) { CP_WAIT1(); } else { CP_WAIT0(); }
        __syncthreads();

        uint32_t aB = smA + (uint32_t)buf * G1_ABUF +
                      (uint32_t)(((wm * 64 + l15) * 136 + acol) * 2);
        uint32_t bB = smB + (uint32_t)buf * G1_ABUF +
                      (uint32_t)(((wn * 64 + brow) * 136 + bcol) * 2);

        float c1[4][8][4];
#pragma unroll
        for (int a = 0; a < 4; a++)
#pragma unroll
            for (int b = 0; b < 8; b++)
#pragma unroll
                for (int k = 0; k < 4; k++) c1[a][b][k] = 0.f;

#pragma unroll
        for (int kk = 0; kk < 8; kk++) {
            uint32_t a[4][4], b[8][2];
#pragma unroll
            for (int mi = 0; mi < 4; mi++)
                ldsm4(a[mi][0], a[mi][1], a[mi][2], a[mi][3],
                      aB + mi * 16 * 272 + kk * 32);
#pragma unroll
            for (int p = 0; p < 4; p++)
                ldsm4(b[2 * p][0], b[2 * p][1], b[2 * p + 1][0], b[2 * p + 1][1],
                      bB + p * 16 * 272 + kk * 32);
#pragma unroll
            for (int mi = 0; mi < 4; mi++)
#pragma unroll
                for (int ni = 0; ni < 8; ni++)
                    MMA_16816(c1[mi][ni], a[mi], b[ni]);
        }

        // Epilogue: four 32x32 chunks per warp, each one (i,j) 2KB block
        int tm = t / 48, tn = t - tm * 48;
#pragma unroll
        for (int cm = 0; cm < 2; cm++) {
#pragma unroll
            for (int cn = 0; cn < 2; cn++) {
#pragma unroll
                for (int mh = 0; mh < 2; mh++) {
#pragma unroll
                    for (int h = 0; h < 2; h++) {
                        uint32_t r[4];
#pragma unroll
                        for (int nb = 0; nb < 4; nb++) {
                            __half2 hv = __floats2half2_rn(
                                c1[cm * 2 + mh][cn * 4 + nb][2 * h],
                                c1[cm * 2 + mh][cn * 4 + nb][2 * h + 1]);
                            r[nb] = *(uint32_t*)&hv;
                        }
                        uint32_t ad = stS +
                            (uint32_t)(((mh * 16 + h * 8 + (lane & 7)) * 40 +
                                        (lane >> 3) * 8) * 2);
                        stsm4(ad, r[0], r[1], r[2], r[3]);
                    }
                }
                __syncwarp();
                int i_ = tm * 4 + wm * 2 + cm;
                int j_ = tn * 8 + wn * 2 + cn;
                char* gb = (char*)(g_G + (((size_t)i_ * I_DIM + j_) << 10));
#pragma unroll
                for (int it = 0; it < 4; it++) {
                    int o = it * 512 + lane * 16;
                    int d = o >> 6, cb = o & 63;
                    uint4 v = *(uint4*)(stage + d * 80 + cb);
                    *(uint4*)(gb + o) = v;
                }
                __syncwarp();
            }
        }
        __syncthreads();
        buf ^= 1;
    }
}

// ---------------- K5: GEMM2  out[(i,j),f] = G * Wt^T + bias, /(norm+1e-3) --
// CTA tile 256(M) x 128(N), K=1024 in 16 chunks of 64, double-buffered.
// 256 threads = 8 warps (wm 0..3 m-slabs of 64, wn 0..1 n-slabs of 64),
// warp tile 64x64, accum c[4][8][4]. Grid = 147456/256 = 576.
// Pipeline: issue next chunk, WAIT1 drains the CURRENT chunk (older group),
// sync, compute, sync, flip.  (Round-12/13 bug: wait was after compute ->
// only the newer group outstanding -> WAIT1 no-op -> raced reads.)
// Smem: As0@0(36864) As1@36864 Bs0@73728(18432) Bs1@92160 -> 110592 B.
#define SM_G2 110592
__global__ __launch_bounds__(256, 1) void k_gemm2(const float* __restrict__ obias,
                                                  float* __restrict__ out) {
    extern __shared__ char sm2_[];
    uint32_t asB = s32(sm2_);
    uint32_t bsB = asB + 73728;

    int tid = threadIdx.x, lane = tid & 31, wid = tid >> 5;
    int wm = wid & 3, wn = wid >> 2;
    int g = lane >> 2, tg = lane & 3;
    int bm = blockIdx.x;
    const __half* Ag = g_G + (size_t)bm * 256 * 1024;

    int l15  = lane & 15;
    int acol = (lane >> 4) << 3;
    int brow = (lane & 7) + ((lane >> 4) << 3);
    int bcol = ((lane >> 3) & 1) << 3;
    uint32_t aB = asB + (uint32_t)(((wm * 64 + l15) * 72 + acol) * 2);
    uint32_t bB = bsB + (uint32_t)(((wn * 64 + brow) * 72 + bcol) * 2);

    int lr = tid >> 3, lc = (tid & 7) * 8;   // 32 rows x 8 uint4 per pass

    auto load_chunk = [&](int kcol, int b) {
        uint32_t aD = asB + (uint32_t)b * 36864;
        uint32_t bD = bsB + (uint32_t)b * 18432;
#pragma unroll
        for (int h = 0; h < 8; h++) {        // A: 256 rows
            int r = lr + h * 32;
            cp16(aD + (uint32_t)((r * 72 + lc) * 2),
                 Ag + (size_t)r * 1024 + kcol + lc);
        }
#pragma unroll
        for (int h = 0; h < 4; h++) {        // B: 128 rows
            int r = lr + h * 32;
            cp16(bD + (uint32_t)((r * 72 + lc) * 2),
                 g_Wt + (size_t)r * 1024 + kcol + lc);
        }
        CP_COMMIT();
    };

    float c2[4][8][4];
#pragma unroll
    for (int a = 0; a < 4; a++)
#pragma unroll
        for (int b = 0; b < 8; b++)
#pragma unroll
            for (int k = 0; k < 4; k++) c2[a][b][k] = 0.f;

    load_chunk(0, 0);                         // G_0

    int buf = 0;
    for (int kc = 0; kc < 16; kc++) {
        if (kc < 15) load_chunk((kc + 1) * 64, buf ^ 1);   // issue G_{kc+1}
        // outstanding: {G_kc (older), G_{kc+1} (newer)} -> WAIT1 drains G_kc
        if (kc < 15) { CP_WAIT1(); } else { CP_WAIT0(); }
        __syncthreads();

        uint32_t oA = (uint32_t)(buf * 36864);
        uint32_t oB = (uint32_t)(buf * 18432);
#pragma unroll
        for (int kk = 0; kk < 4; kk++) {
            uint32_t a[4][4], b[8][2];
#pragma unroll
            for (int mi = 0; mi < 4; mi++)
                ldsm4(a[mi][0], a[mi][1], a[mi][2], a[mi][3],
                      aB + oA + mi * 16 * 144 + kk * 32);
#pragma unroll
            for (int p = 0; p < 4; p++)
                ldsm4(b[2 * p][0], b[2 * p][1], b[2 * p + 1][0], b[2 * p + 1][1],
                      bB + oB + p * 16 * 144 + kk * 32);
#pragma unroll
            for (int mi = 0; mi < 4; mi++)
#pragma unroll
                for (int ni = 0; ni < 8; ni++)
                    MMA_16816(c2[mi][ni], a[mi], b[ni]);
        }
        __syncthreads();        // compute done before next issue overwrites buf
        buf ^= 1;
    }

    // Epilogue: (+bias) / (norm + 0.001)
#pragma unroll
    for (int mi = 0; mi < 4; mi++) {
        int p0 = bm * 256 + wm * 64 + mi * 16 + g;
        float rn0 = 1.f / (g_norm[p0] + 0.001f);
        float rn1 = 1.f / (g_norm[p0 + 8] + 0.001f);
#pragma unroll
        for (int ni = 0; ni < 8; ni++) {
            int f = wn * 64 + ni * 8 + tg * 2;
            float2 bias = *(const float2*)&obias[f];
            float2 o0, o1;
            o0.x = (c2[mi][ni][0] + bias.x) * rn0;
            o0.y = (c2[mi][ni][1] + bias.y) * rn0;
            o1.x = (c2[mi][ni][2] + bias.x) * rn1;
            o1.y = (c2[mi][ni][3] + bias.y) * rn1;
            *(float2*)&out[(size_t)p0 * F_DIM + f] = o0;
            *(float2*)&out[(size_t)(p0 + 8) * F_DIM + f] = o1;
        }
    }
}

// ---------------- launch ---------------------------------------------------
extern "C" void kernel_launch(void* const* d_in, const int* in_sizes, int n_in,
                              void* d_out, int out_size) {
    (void)in_sizes; (void)n_in; (void)out_size;
    const float* node = (const float*)d_in[0];   // (128,384,256)
    const float* mask = (const float*)d_in[1];   // (128,384)
    const float* Wp   = (const float*)d_in[2];   // (256,64)
    const float* bp   = (const float*)d_in[3];   // (64,)
    const float* Wo   = (const float*)d_in[4];   // (32,32,128)
    const float* ob   = (const float*)d_in[5];   // (128,)
    float* out = (float*)d_out;                  // (384,384,128)

    static bool attr_set = false;
    if (!attr_set) {
        cudaFuncSetAttribute(k_ln_proj, cudaFuncAttributeMaxDynamicSharedMemorySize,
                             73728);
        cudaFuncSetAttribute(k_gemm1, cudaFuncAttributeMaxDynamicSharedMemorySize,
                             SM_G1);
        cudaFuncSetAttribute(k_gemm2, cudaFuncAttributeMaxDynamicSharedMemorySize,
                             SM_G2);
        attr_set = true;
    }

    k_ln_proj<<<S_DIM * I_DIM / 64, 256, 73728>>>(node, mask, Wp, bp);
    k_wt<<<(F_DIM * 1024) / 256, 256>>>(Wo);
    k_norm<<<dim3(I_DIM / 32, I_DIM / 32), 256>>>(mask);
    k_gemm1<<<152, 256, SM_G1>>>();
    k_gemm2<<<(I_DIM * I_DIM) / 256, 256, SM_G2>>>(ob, out);
}